// round 13
// baseline (speedup 1.0000x reference)
#include <cuda_runtime.h>
#include <cuda_bf16.h>
#include <cstdint>

// ---------------------------------------------------------------------------
// Swin shifted-window attention. R12: R10's proven GEMM smem layout + register
// double-buffered global loads (overlap LDG latency with FMA2 compute).
// Attention = R11 f32x2 QK/AV with enforced smem alignment.
// ---------------------------------------------------------------------------

#define B_     16
#define HW     56
#define EMB    384
#define HEADS  12
#define HD     32
#define WS     7
#define NTOK   49
#define NWIN   64
#define TOKENS (B_*HW*HW)  // 50176

#define BM 128
#define BN 128
#define BK 16
#define TM 8
#define TN 16
#define NTHR 128

#define KTS 58             // attn kT stride (even -> aligned 8B j-pair reads)

__device__ float g_q[B_*NWIN*HEADS*NTOK*HD];
__device__ float g_k[B_*NWIN*HEADS*NTOK*HD];
__device__ float g_v[B_*NWIN*HEADS*NTOK*HD];
__device__ float g_ao[TOKENS*EMB];

// packed f32x2 helpers (constant-indexed / named operands only)
#define FMA2(C, A, Bv)                                                     \
    asm("fma.rn.f32x2 %0, %1, %2, %0;" : "+l"(C) : "l"(A), "l"(Bv))
#define PACK2(O, LO, HI)                                                   \
    asm("mov.b64 %0, {%1, %2};" : "=l"(O) : "r"(LO), "r"(HI))
#define UNPACK2(LO, HI, I)                                                 \
    asm("mov.b64 {%0, %1}, %2;" : "=r"(LO), "=r"(HI) : "l"(I))

// ---------------------------------------------------------------------------
// Stage 1: QKV GEMM. C[i][j] = sum_k A_rolled[i][k]*Wqkv[j][k].
// smem [BK][BM] (R10-proven). Register double-buffer on global loads.
// ---------------------------------------------------------------------------
__global__ __launch_bounds__(NTHR) void qkv_gemm(const float* __restrict__ x,
                                                 const float* __restrict__ wqkv) {
    __shared__ __align__(16) float As[BK][BM];
    __shared__ __align__(16) float Bs[BK][BN];
    const int tid  = threadIdx.x;
    const int row0 = blockIdx.y * BM;
    const int col0 = blockIdx.x * BN;
    const int tr   = (tid & 15) * TM;
    const int tc   = (tid >> 4) * TN;

    unsigned long long acc2[TM][TN/2];
#pragma unroll
    for (int i = 0; i < TM; i++)
#pragma unroll
        for (int j = 0; j < TN/2; j++) acc2[i][j] = 0ull;

    const int lr0 = tid >> 2;
    const int c4  = tid & 3;
    const float* arow[4];
    const float* brow[4];
#pragma unroll
    for (int l = 0; l < 4; l++) {
        int r = lr0 + l * 32;
        int m = row0 + r;
        int b = m / 3136, rem = m % 3136, h = rem / HW, w = rem % HW;
        int hs = (h + 3) % HW, ws = (w + 3) % HW;   // roll(-3,-3)
        arow[l] = x + ((b * HW + hs) * HW + ws) * EMB;
        brow[l] = wqkv + (col0 + r) * EMB;
    }

    // prologue: load slab 0 into registers
    float4 sa[4], sb[4];
#pragma unroll
    for (int l = 0; l < 4; l++) {
        sa[l] = *(const float4*)(arow[l] + c4 * 4);
        sb[l] = *(const float4*)(brow[l] + c4 * 4);
    }

    for (int k0 = 0; k0 < EMB; k0 += BK) {
        __syncthreads();
#pragma unroll
        for (int l = 0; l < 4; l++) {
            int r = lr0 + l * 32;
            As[c4*4+0][r] = sa[l].x; As[c4*4+1][r] = sa[l].y;
            As[c4*4+2][r] = sa[l].z; As[c4*4+3][r] = sa[l].w;
            Bs[c4*4+0][r] = sb[l].x; Bs[c4*4+1][r] = sb[l].y;
            Bs[c4*4+2][r] = sb[l].z; Bs[c4*4+3][r] = sb[l].w;
        }
        __syncthreads();
        // prefetch next slab while computing this one
        if (k0 + BK < EMB) {
#pragma unroll
            for (int l = 0; l < 4; l++) {
                sa[l] = *(const float4*)(arow[l] + k0 + BK + c4 * 4);
                sb[l] = *(const float4*)(brow[l] + k0 + BK + c4 * 4);
            }
        }
#pragma unroll
        for (int kk = 0; kk < BK; kk++) {
            float af[TM];
            *(float4*)&af[0] = *(float4*)&As[kk][tr];
            *(float4*)&af[4] = *(float4*)&As[kk][tr + 4];
            unsigned long long b2[TN/2];
#pragma unroll
            for (int j = 0; j < TN/2; j++)
                b2[j] = *(const unsigned long long*)&Bs[kk][tc + 2*j];
#pragma unroll
            for (int i = 0; i < TM; i++) {
                unsigned long long a2;
                PACK2(a2, __float_as_uint(af[i]), __float_as_uint(af[i]));
#pragma unroll
                for (int j = 0; j < TN/2; j++) FMA2(acc2[i][j], a2, b2[j]);
            }
        }
    }

    const int sel = col0 / EMB;                   // 0:q 1:k 2:v
    float* dst = (sel == 0) ? g_q : (sel == 1) ? g_k : g_v;
    const int local = col0 + tc - sel * EMB;
    const int head  = local >> 5;
    const int d0    = local & 31;
#pragma unroll
    for (int i = 0; i < TM; i++) {
        int m = row0 + tr + i;
        int b = m / 3136, rem = m % 3136, h = rem / HW, w = rem % HW;
        int win = (h / WS) * 8 + (w / WS);
        int n   = (h % WS) * WS + (w % WS);
        float* drow = dst + (b * NWIN + win) * (HEADS * NTOK * HD)
                          + head * (NTOK * HD) + n * HD + d0;
#pragma unroll
        for (int j = 0; j < TN/2; j += 2) {
            uint32_t l0, h0_, l1, h1_;
            UNPACK2(l0, h0_, acc2[i][j]);
            UNPACK2(l1, h1_, acc2[i][j+1]);
            *(float4*)&drow[2*j] = make_float4(__uint_as_float(l0), __uint_as_float(h0_),
                                               __uint_as_float(l1), __uint_as_float(h1_));
        }
    }
}

// ---------------------------------------------------------------------------
// Stage 2: attention. f32x2 QK (j-pairs) and AV (d-pairs). Aligned smem.
// ---------------------------------------------------------------------------
__global__ __launch_bounds__(256) void attn_kernel(const float* __restrict__ pe_g) {
    __shared__ __align__(16) float q[NTOK * HD];
    __shared__ __align__(16) float kT[HD * KTS];
    __shared__ __align__(16) float v[NTOK * HD];
    __shared__ __align__(16) float sc[NTOK][NTOK + 1];
    __shared__ float pe[169];

    const int blk = blockIdx.x;
    const int tid = threadIdx.x;
    const float* qp = g_q + blk * (NTOK * HD);
    const float* kp = g_k + blk * (NTOK * HD);
    const float* vp = g_v + blk * (NTOK * HD);

    for (int i4 = tid; i4 < NTOK * HD / 4; i4 += 256) {
        ((float4*)q)[i4] = ((const float4*)qp)[i4];
        ((float4*)v)[i4] = ((const float4*)vp)[i4];
    }
    for (int idx = tid; idx < NTOK * HD; idx += 256) {
        kT[(idx & 31) * KTS + (idx >> 5)] = kp[idx];
    }
    if (tid < HD) kT[tid * KTS + 49] = 0.f;   // pad for j-pair reads
    if (tid < 169) pe[tid] = pe_g[tid];
    __syncthreads();

    const int bwin = blk / HEADS;
    const int win  = bwin & 63;
    const int b    = bwin >> 6;
    const bool mUL = (win >= 56);
    const bool mLR = ((win & 7) == 7);
    const float scale = 0.17677669529663687f;

    // QK: each task computes scores (i, 2jp) and (i, 2jp+1)
    for (int task = tid; task < NTOK * 25; task += 256) {
        int i = task / 25, jp = task - i * 25;
        int j0 = jp * 2;
        const float* qi = q + i * HD;
        unsigned long long s2 = 0ull;
#pragma unroll
        for (int d = 0; d < HD; d++) {
            uint32_t qv = __float_as_uint(qi[d]);
            unsigned long long a2;
            PACK2(a2, qv, qv);
            unsigned long long k2 = *(const unsigned long long*)&kT[d * KTS + j0];
            FMA2(s2, a2, k2);
        }
        uint32_t u0, u1;
        UNPACK2(u0, u1, s2);
        int xi = i / WS, yi = i - xi * WS;
        {
            int j = j0, xj = j / WS, yj = j - xj * WS;
            float s = __uint_as_float(u0) * scale + pe[(xj - xi + 6) * 13 + (yj - yi + 6)];
            bool dead = (mUL && ((i >= 28) != (j >= 28))) ||
                        (mLR && ((yi >= 4) != (yj >= 4)));
            sc[i][j] = dead ? -1e30f : s;
        }
        if (j0 + 1 < NTOK) {
            int j = j0 + 1, xj = j / WS, yj = j - xj * WS;
            float s = __uint_as_float(u1) * scale + pe[(xj - xi + 6) * 13 + (yj - yi + 6)];
            bool dead = (mUL && ((i >= 28) != (j >= 28))) ||
                        (mLR && ((yi >= 4) != (yj >= 4)));
            sc[i][j] = dead ? -1e30f : s;
        }
    }
    __syncthreads();

    const int warp = tid >> 5, lane = tid & 31;
    for (int i = warp; i < NTOK; i += 8) {
        float mx = -1e30f;
        for (int j = lane; j < NTOK; j += 32) mx = fmaxf(mx, sc[i][j]);
#pragma unroll
        for (int o = 16; o; o >>= 1) mx = fmaxf(mx, __shfl_xor_sync(0xffffffffu, mx, o));
        float sum = 0.f;
        for (int j = lane; j < NTOK; j += 32) {
            float e = __expf(sc[i][j] - mx);
            sc[i][j] = e;
            sum += e;
        }
#pragma unroll
        for (int o = 16; o; o >>= 1) sum += __shfl_xor_sync(0xffffffffu, sum, o);
        float inv = 1.0f / sum;
        for (int j = lane; j < NTOK; j += 32) sc[i][j] *= inv;
    }
    __syncthreads();

    // AV: each task computes out (i, 2dp) and (i, 2dp+1)
    const int h0 = (win >> 3) * WS, w0 = (win & 7) * WS;
    for (int task = tid; task < NTOK * 16; task += 256) {
        int i = task >> 4, dp = task & 15;
        unsigned long long o2 = 0ull;
#pragma unroll
        for (int j = 0; j < NTOK; j++) {
            uint32_t av = __float_as_uint(sc[i][j]);
            unsigned long long a2;
            PACK2(a2, av, av);
            unsigned long long v2 = *(const unsigned long long*)&v[j * HD + 2 * dp];
            FMA2(o2, a2, v2);
        }
        uint32_t u0, u1;
        UNPACK2(u0, u1, o2);
        int h = h0 + i / WS, w = w0 + i % WS;
        *(float2*)&g_ao[((b * HW + h) * HW + w) * EMB + (blk % HEADS) * HD + 2 * dp] =
            make_float2(__uint_as_float(u0), __uint_as_float(u1));
    }
}

// ---------------------------------------------------------------------------
// Stage 3: projection GEMM (same structure as qkv; +bias, roll(+3,+3)).
// ---------------------------------------------------------------------------
__global__ __launch_bounds__(NTHR) void proj_gemm(const float* __restrict__ wout,
                                                  const float* __restrict__ bout,
                                                  float* __restrict__ out) {
    __shared__ __align__(16) float As[BK][BM];
    __shared__ __align__(16) float Bs[BK][BN];
    const int tid  = threadIdx.x;
    const int row0 = blockIdx.y * BM;
    const int col0 = blockIdx.x * BN;
    const int tr   = (tid & 15) * TM;
    const int tc   = (tid >> 4) * TN;

    unsigned long long acc2[TM][TN/2];
#pragma unroll
    for (int i = 0; i < TM; i++)
#pragma unroll
        for (int j = 0; j < TN/2; j++) acc2[i][j] = 0ull;

    const int lr0 = tid >> 2;
    const int c4  = tid & 3;
    const float* arow[4];
    const float* brow[4];
#pragma unroll
    for (int l = 0; l < 4; l++) {
        int r = lr0 + l * 32;
        arow[l] = g_ao + (row0 + r) * EMB;
        brow[l] = wout + (col0 + r) * EMB;
    }

    float4 sa[4], sb[4];
#pragma unroll
    for (int l = 0; l < 4; l++) {
        sa[l] = *(const float4*)(arow[l] + c4 * 4);
        sb[l] = *(const float4*)(brow[l] + c4 * 4);
    }

    for (int k0 = 0; k0 < EMB; k0 += BK) {
        __syncthreads();
#pragma unroll
        for (int l = 0; l < 4; l++) {
            int r = lr0 + l * 32;
            As[c4*4+0][r] = sa[l].x; As[c4*4+1][r] = sa[l].y;
            As[c4*4+2][r] = sa[l].z; As[c4*4+3][r] = sa[l].w;
            Bs[c4*4+0][r] = sb[l].x; Bs[c4*4+1][r] = sb[l].y;
            Bs[c4*4+2][r] = sb[l].z; Bs[c4*4+3][r] = sb[l].w;
        }
        __syncthreads();
        if (k0 + BK < EMB) {
#pragma unroll
            for (int l = 0; l < 4; l++) {
                sa[l] = *(const float4*)(arow[l] + k0 + BK + c4 * 4);
                sb[l] = *(const float4*)(brow[l] + k0 + BK + c4 * 4);
            }
        }
#pragma unroll
        for (int kk = 0; kk < BK; kk++) {
            float af[TM];
            *(float4*)&af[0] = *(float4*)&As[kk][tr];
            *(float4*)&af[4] = *(float4*)&As[kk][tr + 4];
            unsigned long long b2[TN/2];
#pragma unroll
            for (int j = 0; j < TN/2; j++)
                b2[j] = *(const unsigned long long*)&Bs[kk][tc + 2*j];
#pragma unroll
            for (int i = 0; i < TM; i++) {
                unsigned long long a2;
                PACK2(a2, __float_as_uint(af[i]), __float_as_uint(af[i]));
#pragma unroll
                for (int j = 0; j < TN/2; j++) FMA2(acc2[i][j], a2, b2[j]);
            }
        }
    }

#pragma unroll
    for (int i = 0; i < TM; i++) {
        int m = row0 + tr + i;
        int b = m / 3136, rem = m % 3136, h = rem / HW, w = rem % HW;
        int ho = (h + 3) % HW, wo = (w + 3) % HW;   // roll(+3,+3)
        float* orow = out + ((b * HW + ho) * HW + wo) * EMB + col0 + tc;
#pragma unroll
        for (int j = 0; j < TN/2; j += 2) {
            uint32_t l0, h0_, l1, h1_;
            UNPACK2(l0, h0_, acc2[i][j]);
            UNPACK2(l1, h1_, acc2[i][j+1]);
            float4 bb = *(const float4*)&bout[col0 + tc + 2*j];
            *(float4*)&orow[2*j] = make_float4(__uint_as_float(l0) + bb.x,
                                               __uint_as_float(h0_) + bb.y,
                                               __uint_as_float(l1) + bb.z,
                                               __uint_as_float(h1_) + bb.w);
        }
    }
}

// ---------------------------------------------------------------------------
extern "C" void kernel_launch(void* const* d_in, const int* in_sizes, int n_in,
                              void* d_out, int out_size) {
    const float* x       = (const float*)d_in[0];
    const float* w_qkv   = (const float*)d_in[1];
    const float* pos_emb = (const float*)d_in[2];
    const float* w_out   = (const float*)d_in[3];
    const float* b_out   = (const float*)d_in[4];
    float* out = (float*)d_out;

    dim3 g1(1152 / BN, TOKENS / BM);          // 9 x 392
    qkv_gemm<<<g1, NTHR>>>(x, w_qkv);

    attn_kernel<<<B_ * NWIN * HEADS, 256>>>(pos_emb);

    dim3 g3(EMB / BN, TOKENS / BM);           // 3 x 392
    proj_gemm<<<g3, NTHR>>>(w_out, b_out, out);
}

// round 14
// speedup vs baseline: 1.0891x; 1.0891x over previous
#include <cuda_runtime.h>
#include <cuda_bf16.h>
#include <cstdint>

// ---------------------------------------------------------------------------
// Swin shifted-window attention. R13: R12 GEMMs (reg double-buffer f32x2,
// qkv measured 972us) + warp-per-row fused attention (register softmax,
// shfl-broadcast Q and probs, no sc array, 1 syncthreads).
// ---------------------------------------------------------------------------

#define B_     16
#define HW     56
#define EMB    384
#define HEADS  12
#define HD     32
#define WS     7
#define NTOK   49
#define NWIN   64
#define TOKENS (B_*HW*HW)  // 50176

#define BM 128
#define BN 128
#define BK 16
#define TM 8
#define TN 16
#define NTHR 128

#define KTS 57             // attn kT stride (odd -> conflict-free)

__device__ float g_q[B_*NWIN*HEADS*NTOK*HD];
__device__ float g_k[B_*NWIN*HEADS*NTOK*HD];
__device__ float g_v[B_*NWIN*HEADS*NTOK*HD];
__device__ float g_ao[TOKENS*EMB];

#define FMA2(C, A, Bv)                                                     \
    asm("fma.rn.f32x2 %0, %1, %2, %0;" : "+l"(C) : "l"(A), "l"(Bv))
#define PACK2(O, LO, HI)                                                   \
    asm("mov.b64 %0, {%1, %2};" : "=l"(O) : "r"(LO), "r"(HI))
#define UNPACK2(LO, HI, I)                                                 \
    asm("mov.b64 {%0, %1}, %2;" : "=r"(LO), "=r"(HI) : "l"(I))

// ---------------------------------------------------------------------------
// Stage 1: QKV GEMM (identical to R12 passing version, 972us).
// ---------------------------------------------------------------------------
__global__ __launch_bounds__(NTHR) void qkv_gemm(const float* __restrict__ x,
                                                 const float* __restrict__ wqkv) {
    __shared__ __align__(16) float As[BK][BM];
    __shared__ __align__(16) float Bs[BK][BN];
    const int tid  = threadIdx.x;
    const int row0 = blockIdx.y * BM;
    const int col0 = blockIdx.x * BN;
    const int tr   = (tid & 15) * TM;
    const int tc   = (tid >> 4) * TN;

    unsigned long long acc2[TM][TN/2];
#pragma unroll
    for (int i = 0; i < TM; i++)
#pragma unroll
        for (int j = 0; j < TN/2; j++) acc2[i][j] = 0ull;

    const int lr0 = tid >> 2;
    const int c4  = tid & 3;
    const float* arow[4];
    const float* brow[4];
#pragma unroll
    for (int l = 0; l < 4; l++) {
        int r = lr0 + l * 32;
        int m = row0 + r;
        int b = m / 3136, rem = m % 3136, h = rem / HW, w = rem % HW;
        int hs = (h + 3) % HW, ws = (w + 3) % HW;   // roll(-3,-3)
        arow[l] = x + ((b * HW + hs) * HW + ws) * EMB;
        brow[l] = wqkv + (col0 + r) * EMB;
    }

    float4 sa[4], sb[4];
#pragma unroll
    for (int l = 0; l < 4; l++) {
        sa[l] = *(const float4*)(arow[l] + c4 * 4);
        sb[l] = *(const float4*)(brow[l] + c4 * 4);
    }

    for (int k0 = 0; k0 < EMB; k0 += BK) {
        __syncthreads();
#pragma unroll
        for (int l = 0; l < 4; l++) {
            int r = lr0 + l * 32;
            As[c4*4+0][r] = sa[l].x; As[c4*4+1][r] = sa[l].y;
            As[c4*4+2][r] = sa[l].z; As[c4*4+3][r] = sa[l].w;
            Bs[c4*4+0][r] = sb[l].x; Bs[c4*4+1][r] = sb[l].y;
            Bs[c4*4+2][r] = sb[l].z; Bs[c4*4+3][r] = sb[l].w;
        }
        __syncthreads();
        if (k0 + BK < EMB) {
#pragma unroll
            for (int l = 0; l < 4; l++) {
                sa[l] = *(const float4*)(arow[l] + k0 + BK + c4 * 4);
                sb[l] = *(const float4*)(brow[l] + k0 + BK + c4 * 4);
            }
        }
#pragma unroll
        for (int kk = 0; kk < BK; kk++) {
            float af[TM];
            *(float4*)&af[0] = *(float4*)&As[kk][tr];
            *(float4*)&af[4] = *(float4*)&As[kk][tr + 4];
            unsigned long long b2[TN/2];
#pragma unroll
            for (int j = 0; j < TN/2; j++)
                b2[j] = *(const unsigned long long*)&Bs[kk][tc + 2*j];
#pragma unroll
            for (int i = 0; i < TM; i++) {
                unsigned long long a2;
                PACK2(a2, __float_as_uint(af[i]), __float_as_uint(af[i]));
#pragma unroll
                for (int j = 0; j < TN/2; j++) FMA2(acc2[i][j], a2, b2[j]);
            }
        }
    }

    const int sel = col0 / EMB;
    float* dst = (sel == 0) ? g_q : (sel == 1) ? g_k : g_v;
    const int local = col0 + tc - sel * EMB;
    const int head  = local >> 5;
    const int d0    = local & 31;
#pragma unroll
    for (int i = 0; i < TM; i++) {
        int m = row0 + tr + i;
        int b = m / 3136, rem = m % 3136, h = rem / HW, w = rem % HW;
        int win = (h / WS) * 8 + (w / WS);
        int n   = (h % WS) * WS + (w % WS);
        float* drow = dst + (b * NWIN + win) * (HEADS * NTOK * HD)
                          + head * (NTOK * HD) + n * HD + d0;
#pragma unroll
        for (int j = 0; j < TN/2; j += 2) {
            uint32_t l0, h0_, l1, h1_;
            UNPACK2(l0, h0_, acc2[i][j]);
            UNPACK2(l1, h1_, acc2[i][j+1]);
            *(float4*)&drow[2*j] = make_float4(__uint_as_float(l0), __uint_as_float(h0_),
                                               __uint_as_float(l1), __uint_as_float(h1_));
        }
    }
}

// ---------------------------------------------------------------------------
// Stage 2: attention. One block per (b, win, head), 256 threads = 8 warps.
// Warp w handles rows i = w, w+8, ... Lane covers j in {lane, 32+lane}.
// Softmax + AV fully in registers (shfl broadcast). One __syncthreads.
// ---------------------------------------------------------------------------
__global__ __launch_bounds__(256) void attn_kernel(const float* __restrict__ pe_g) {
    __shared__ __align__(16) float q[NTOK * HD];
    __shared__ __align__(16) float kT[HD * KTS + 48];  // pad: lanes>=17 read past row
    __shared__ __align__(16) float v[NTOK * HD];
    __shared__ float pe[169];

    const int blk = blockIdx.x;
    const int tid = threadIdx.x;
    const float* qp = g_q + blk * (NTOK * HD);
    const float* kp = g_k + blk * (NTOK * HD);
    const float* vp = g_v + blk * (NTOK * HD);

    for (int i4 = tid; i4 < NTOK * HD / 4; i4 += 256) {
        ((float4*)q)[i4] = ((const float4*)qp)[i4];
        ((float4*)v)[i4] = ((const float4*)vp)[i4];
    }
    for (int idx = tid; idx < NTOK * HD; idx += 256) {
        kT[(idx & 31) * KTS + (idx >> 5)] = kp[idx];
    }
    if (tid < 169) pe[tid] = pe_g[tid];
    __syncthreads();

    const int head = blk % HEADS;
    const int bwin = blk / HEADS;
    const int win  = bwin & 63;
    const int b    = bwin >> 6;
    const bool mUL = (win >= 56);
    const bool mLR = ((win & 7) == 7);
    const float scale = 0.17677669529663687f;  // 1/sqrt(32)
    const int warp = tid >> 5, lane = tid & 31;
    const int h0 = (win >> 3) * WS, w0 = (win & 7) * WS;

    for (int i = warp; i < NTOK; i += 8) {
        // ---- QK: scores for j0 = lane, j1 = 32+lane ----
        float qreg = q[i * HD + lane];
        float s0 = 0.f, s1 = 0.f;
#pragma unroll
        for (int d = 0; d < HD; d++) {
            float qv = __shfl_sync(0xffffffffu, qreg, d);
            s0 = fmaf(qv, kT[d * KTS + lane], s0);
            s1 = fmaf(qv, kT[d * KTS + 32 + lane], s1);  // garbage for lane>=17, discarded
        }
        // ---- bias + mask ----
        const int xi = i / WS, yi = i - xi * WS;
        float sc0, sc1 = -1e30f;
        {
            int j = lane, xj = j / WS, yj = j - xj * WS;
            float s = s0 * scale + pe[(xj - xi + 6) * 13 + (yj - yi + 6)];
            bool dead = (mUL && ((i >= 28) != (j >= 28))) ||
                        (mLR && ((yi >= 4) != (yj >= 4)));
            sc0 = dead ? -1e30f : s;
        }
        if (lane < 17) {
            int j = 32 + lane, xj = j / WS, yj = j - xj * WS;
            float s = s1 * scale + pe[(xj - xi + 6) * 13 + (yj - yi + 6)];
            bool dead = (mUL && ((i >= 28) != (j >= 28))) ||
                        (mLR && ((yi >= 4) != (yj >= 4)));
            sc1 = dead ? -1e30f : s;
        }
        // ---- softmax in registers ----
        float mx = fmaxf(sc0, sc1);
#pragma unroll
        for (int o = 16; o; o >>= 1) mx = fmaxf(mx, __shfl_xor_sync(0xffffffffu, mx, o));
        float e0 = __expf(sc0 - mx);
        float e1 = (lane < 17) ? __expf(sc1 - mx) : 0.f;
        float sum = e0 + e1;
#pragma unroll
        for (int o = 16; o; o >>= 1) sum += __shfl_xor_sync(0xffffffffu, sum, o);
        float inv = 1.0f / sum;
        float p0 = e0 * inv, p1 = e1 * inv;
        // ---- AV: lane = d ----
        float o = 0.f;
#pragma unroll
        for (int j = 0; j < 32; j++)
            o = fmaf(__shfl_sync(0xffffffffu, p0, j), v[j * HD + lane], o);
#pragma unroll
        for (int j = 0; j < 17; j++)
            o = fmaf(__shfl_sync(0xffffffffu, p1, j), v[(32 + j) * HD + lane], o);
        // ---- store (token layout, rolled coords) ----
        int h = h0 + i / WS, w = w0 + i % WS;
        g_ao[((b * HW + h) * HW + w) * EMB + head * HD + lane] = o;
    }
}

// ---------------------------------------------------------------------------
// Stage 3: projection GEMM (identical to R12 passing version).
// ---------------------------------------------------------------------------
__global__ __launch_bounds__(NTHR) void proj_gemm(const float* __restrict__ wout,
                                                  const float* __restrict__ bout,
                                                  float* __restrict__ out) {
    __shared__ __align__(16) float As[BK][BM];
    __shared__ __align__(16) float Bs[BK][BN];
    const int tid  = threadIdx.x;
    const int row0 = blockIdx.y * BM;
    const int col0 = blockIdx.x * BN;
    const int tr   = (tid & 15) * TM;
    const int tc   = (tid >> 4) * TN;

    unsigned long long acc2[TM][TN/2];
#pragma unroll
    for (int i = 0; i < TM; i++)
#pragma unroll
        for (int j = 0; j < TN/2; j++) acc2[i][j] = 0ull;

    const int lr0 = tid >> 2;
    const int c4  = tid & 3;
    const float* arow[4];
    const float* brow[4];
#pragma unroll
    for (int l = 0; l < 4; l++) {
        int r = lr0 + l * 32;
        arow[l] = g_ao + (row0 + r) * EMB;
        brow[l] = wout + (col0 + r) * EMB;
    }

    float4 sa[4], sb[4];
#pragma unroll
    for (int l = 0; l < 4; l++) {
        sa[l] = *(const float4*)(arow[l] + c4 * 4);
        sb[l] = *(const float4*)(brow[l] + c4 * 4);
    }

    for (int k0 = 0; k0 < EMB; k0 += BK) {
        __syncthreads();
#pragma unroll
        for (int l = 0; l < 4; l++) {
            int r = lr0 + l * 32;
            As[c4*4+0][r] = sa[l].x; As[c4*4+1][r] = sa[l].y;
            As[c4*4+2][r] = sa[l].z; As[c4*4+3][r] = sa[l].w;
            Bs[c4*4+0][r] = sb[l].x; Bs[c4*4+1][r] = sb[l].y;
            Bs[c4*4+2][r] = sb[l].z; Bs[c4*4+3][r] = sb[l].w;
        }
        __syncthreads();
        if (k0 + BK < EMB) {
#pragma unroll
            for (int l = 0; l < 4; l++) {
                sa[l] = *(const float4*)(arow[l] + k0 + BK + c4 * 4);
                sb[l] = *(const float4*)(brow[l] + k0 + BK + c4 * 4);
            }
        }
#pragma unroll
        for (int kk = 0; kk < BK; kk++) {
            float af[TM];
            *(float4*)&af[0] = *(float4*)&As[kk][tr];
            *(float4*)&af[4] = *(float4*)&As[kk][tr + 4];
            unsigned long long b2[TN/2];
#pragma unroll
            for (int j = 0; j < TN/2; j++)
                b2[j] = *(const unsigned long long*)&Bs[kk][tc + 2*j];
#pragma unroll
            for (int i = 0; i < TM; i++) {
                unsigned long long a2;
                PACK2(a2, __float_as_uint(af[i]), __float_as_uint(af[i]));
#pragma unroll
                for (int j = 0; j < TN/2; j++) FMA2(acc2[i][j], a2, b2[j]);
            }
        }
    }

#pragma unroll
    for (int i = 0; i < TM; i++) {
        int m = row0 + tr + i;
        int b = m / 3136, rem = m % 3136, h = rem / HW, w = rem % HW;
        int ho = (h + 3) % HW, wo = (w + 3) % HW;   // roll(+3,+3)
        float* orow = out + ((b * HW + ho) * HW + wo) * EMB + col0 + tc;
#pragma unroll
        for (int j = 0; j < TN/2; j += 2) {
            uint32_t l0, h0_, l1, h1_;
            UNPACK2(l0, h0_, acc2[i][j]);
            UNPACK2(l1, h1_, acc2[i][j+1]);
            float4 bb = *(const float4*)&bout[col0 + tc + 2*j];
            *(float4*)&orow[2*j] = make_float4(__uint_as_float(l0) + bb.x,
                                               __uint_as_float(h0_) + bb.y,
                                               __uint_as_float(l1) + bb.z,
                                               __uint_as_float(h1_) + bb.w);
        }
    }
}

// ---------------------------------------------------------------------------
extern "C" void kernel_launch(void* const* d_in, const int* in_sizes, int n_in,
                              void* d_out, int out_size) {
    const float* x       = (const float*)d_in[0];
    const float* w_qkv   = (const float*)d_in[1];
    const float* pos_emb = (const float*)d_in[2];
    const float* w_out   = (const float*)d_in[3];
    const float* b_out   = (const float*)d_in[4];
    float* out = (float*)d_out;

    dim3 g1(1152 / BN, TOKENS / BM);          // 9 x 392
    qkv_gemm<<<g1, NTHR>>>(x, w_qkv);

    attn_kernel<<<B_ * NWIN * HEADS, 256>>>(pos_emb);

    dim3 g3(EMB / BN, TOKENS / BM);           // 3 x 392
    proj_gemm<<<g3, NTHR>>>(w_out, b_out, out);
}

// round 15
// speedup vs baseline: 1.2622x; 1.1590x over previous
#include <cuda_runtime.h>
#include <cuda_bf16.h>
#include <cstdint>

// ---------------------------------------------------------------------------
// Swin shifted-window attention. R14: GEMMs get smem double-buffering (1 sync
// per slab) + STS bank-conflict fix (row stride BM+4). Attention gets 2-row
// per-warp ILP. All constructs guard-proven (no mma/wmma/cp.async).
// ---------------------------------------------------------------------------

#define B_     16
#define HW     56
#define EMB    384
#define HEADS  12
#define HD     32
#define WS     7
#define NTOK   49
#define NWIN   64
#define TOKENS (B_*HW*HW)  // 50176

#define BM 128
#define BN 128
#define BK 16
#define TM 8
#define TN 16
#define NTHR 128
#define BMP (BM + 4)       // padded smem row stride: STS conflicts 4-way -> 2-way

#define KTS 57             // attn kT stride (odd -> conflict-free)

__device__ float g_q[B_*NWIN*HEADS*NTOK*HD];
__device__ float g_k[B_*NWIN*HEADS*NTOK*HD];
__device__ float g_v[B_*NWIN*HEADS*NTOK*HD];
__device__ float g_ao[TOKENS*EMB];

#define FMA2(C, A, Bv)                                                     \
    asm("fma.rn.f32x2 %0, %1, %2, %0;" : "+l"(C) : "l"(A), "l"(Bv))
#define PACK2(O, LO, HI)                                                   \
    asm("mov.b64 %0, {%1, %2};" : "=l"(O) : "r"(LO), "r"(HI))
#define UNPACK2(LO, HI, I)                                                 \
    asm("mov.b64 {%0, %1}, %2;" : "=r"(LO), "=r"(HI) : "l"(I))

// ---------------------------------------------------------------------------
// GEMM main loop (shared shape): smem[2] ping-pong, register-staged LDG.
// iter s: sync; STS slab s+1 -> smem[cur^1]; LDG slab s+2 -> regs;
//         compute smem[cur].
// ---------------------------------------------------------------------------
#define GEMM_MAIN_LOOP                                                        \
    do {                                                                      \
        /* prologue: slab0 -> smem[0], slab1 -> regs */                       \
        _Pragma("unroll")                                                     \
        for (int l = 0; l < 4; l++) {                                         \
            float4 a = *(const float4*)(arow[l] + c4 * 4);                    \
            float4 bv = *(const float4*)(brow[l] + c4 * 4);                   \
            int r = lr0 + l * 32;                                             \
            As[0][c4*4+0][r] = a.x; As[0][c4*4+1][r] = a.y;                   \
            As[0][c4*4+2][r] = a.z; As[0][c4*4+3][r] = a.w;                   \
            Bs[0][c4*4+0][r] = bv.x; Bs[0][c4*4+1][r] = bv.y;                 \
            Bs[0][c4*4+2][r] = bv.z; Bs[0][c4*4+3][r] = bv.w;                 \
        }                                                                     \
        _Pragma("unroll")                                                     \
        for (int l = 0; l < 4; l++) {                                         \
            sa[l] = *(const float4*)(arow[l] + BK + c4 * 4);                  \
            sb[l] = *(const float4*)(brow[l] + BK + c4 * 4);                  \
        }                                                                     \
        _Pragma("unroll 1")                                                   \
        for (int s = 0; s < EMB / BK; s++) {                                  \
            const int cur = s & 1;                                            \
            __syncthreads();                                                  \
            if (s + 1 < EMB / BK) {                                           \
                const int nxt = cur ^ 1;                                      \
                _Pragma("unroll")                                             \
                for (int l = 0; l < 4; l++) {                                 \
                    int r = lr0 + l * 32;                                     \
                    As[nxt][c4*4+0][r] = sa[l].x; As[nxt][c4*4+1][r] = sa[l].y; \
                    As[nxt][c4*4+2][r] = sa[l].z; As[nxt][c4*4+3][r] = sa[l].w; \
                    Bs[nxt][c4*4+0][r] = sb[l].x; Bs[nxt][c4*4+1][r] = sb[l].y; \
                    Bs[nxt][c4*4+2][r] = sb[l].z; Bs[nxt][c4*4+3][r] = sb[l].w; \
                }                                                             \
                if (s + 2 < EMB / BK) {                                       \
                    const int k2 = (s + 2) * BK;                              \
                    _Pragma("unroll")                                         \
                    for (int l = 0; l < 4; l++) {                             \
                        sa[l] = *(const float4*)(arow[l] + k2 + c4 * 4);      \
                        sb[l] = *(const float4*)(brow[l] + k2 + c4 * 4);      \
                    }                                                         \
                }                                                             \
            }                                                                 \
            _Pragma("unroll")                                                 \
            for (int kk = 0; kk < BK; kk++) {                                 \
                float af[TM];                                                 \
                *(float4*)&af[0] = *(float4*)&As[cur][kk][tr];                \
                *(float4*)&af[4] = *(float4*)&As[cur][kk][tr + 4];            \
                unsigned long long b2[TN/2];                                  \
                _Pragma("unroll")                                             \
                for (int j = 0; j < TN/2; j++)                                \
                    b2[j] = *(const unsigned long long*)&Bs[cur][kk][tc + 2*j]; \
                _Pragma("unroll")                                             \
                for (int i = 0; i < TM; i++) {                                \
                    unsigned long long a2;                                    \
                    PACK2(a2, __float_as_uint(af[i]), __float_as_uint(af[i])); \
                    _Pragma("unroll")                                         \
                    for (int j = 0; j < TN/2; j++) FMA2(acc2[i][j], a2, b2[j]); \
                }                                                             \
            }                                                                 \
        }                                                                     \
    } while (0)

// ---------------------------------------------------------------------------
// Stage 1: QKV GEMM.
// ---------------------------------------------------------------------------
__global__ __launch_bounds__(NTHR) void qkv_gemm(const float* __restrict__ x,
                                                 const float* __restrict__ wqkv) {
    __shared__ __align__(16) float As[2][BK][BMP];
    __shared__ __align__(16) float Bs[2][BK][BMP];
    const int tid  = threadIdx.x;
    const int row0 = blockIdx.y * BM;
    const int col0 = blockIdx.x * BN;
    const int tr   = (tid & 15) * TM;
    const int tc   = (tid >> 4) * TN;

    unsigned long long acc2[TM][TN/2];
#pragma unroll
    for (int i = 0; i < TM; i++)
#pragma unroll
        for (int j = 0; j < TN/2; j++) acc2[i][j] = 0ull;

    const int lr0 = tid >> 2;
    const int c4  = tid & 3;
    const float* arow[4];
    const float* brow[4];
#pragma unroll
    for (int l = 0; l < 4; l++) {
        int r = lr0 + l * 32;
        int m = row0 + r;
        int b = m / 3136, rem = m % 3136, h = rem / HW, w = rem % HW;
        int hs = (h + 3) % HW, ws = (w + 3) % HW;   // roll(-3,-3)
        arow[l] = x + ((b * HW + hs) * HW + ws) * EMB;
        brow[l] = wqkv + (col0 + r) * EMB;
    }
    float4 sa[4], sb[4];

    GEMM_MAIN_LOOP;

    const int sel = col0 / EMB;                   // 0:q 1:k 2:v
    float* dst = (sel == 0) ? g_q : (sel == 1) ? g_k : g_v;
    const int local = col0 + tc - sel * EMB;
    const int head  = local >> 5;
    const int d0    = local & 31;
#pragma unroll
    for (int i = 0; i < TM; i++) {
        int m = row0 + tr + i;
        int b = m / 3136, rem = m % 3136, h = rem / HW, w = rem % HW;
        int win = (h / WS) * 8 + (w / WS);
        int n   = (h % WS) * WS + (w % WS);
        float* drow = dst + (b * NWIN + win) * (HEADS * NTOK * HD)
                          + head * (NTOK * HD) + n * HD + d0;
#pragma unroll
        for (int j = 0; j < TN/2; j += 2) {
            uint32_t l0, h0_, l1, h1_;
            UNPACK2(l0, h0_, acc2[i][j]);
            UNPACK2(l1, h1_, acc2[i][j+1]);
            *(float4*)&drow[2*j] = make_float4(__uint_as_float(l0), __uint_as_float(h0_),
                                               __uint_as_float(l1), __uint_as_float(h1_));
        }
    }
}

// ---------------------------------------------------------------------------
// Stage 2: attention. Warp-per-row fused, TWO rows per iteration for ILP.
// ---------------------------------------------------------------------------
__global__ __launch_bounds__(256) void attn_kernel(const float* __restrict__ pe_g) {
    __shared__ __align__(16) float q[NTOK * HD];
    __shared__ __align__(16) float kT[HD * KTS + 48];
    __shared__ __align__(16) float v[NTOK * HD];
    __shared__ float pe[169];

    const int blk = blockIdx.x;
    const int tid = threadIdx.x;
    const float* qp = g_q + blk * (NTOK * HD);
    const float* kp = g_k + blk * (NTOK * HD);
    const float* vp = g_v + blk * (NTOK * HD);

    for (int i4 = tid; i4 < NTOK * HD / 4; i4 += 256) {
        ((float4*)q)[i4] = ((const float4*)qp)[i4];
        ((float4*)v)[i4] = ((const float4*)vp)[i4];
    }
    for (int idx = tid; idx < NTOK * HD; idx += 256) {
        kT[(idx & 31) * KTS + (idx >> 5)] = kp[idx];
    }
    if (tid < 169) pe[tid] = pe_g[tid];
    __syncthreads();

    const int head = blk % HEADS;
    const int bwin = blk / HEADS;
    const int win  = bwin & 63;
    const int b    = bwin >> 6;
    const bool mUL = (win >= 56);
    const bool mLR = ((win & 7) == 7);
    const float scale = 0.17677669529663687f;  // 1/sqrt(32)
    const int warp = tid >> 5, lane = tid & 31;
    const int h0 = (win >> 3) * WS, w0 = (win & 7) * WS;

    for (int i = warp; i < NTOK; i += 16) {
        const int i2 = i + 8;
        const bool two = (i2 < NTOK);           // warp-uniform
        // ---- QK: interleaved for rows i and i2 ----
        float qA = q[i * HD + lane];
        float qB = two ? q[i2 * HD + lane] : 0.f;
        float sA0 = 0.f, sA1 = 0.f, sB0 = 0.f, sB1 = 0.f;
#pragma unroll
        for (int d = 0; d < HD; d++) {
            float k0v = kT[d * KTS + lane];
            float k1v = kT[d * KTS + 32 + lane];
            float qa = __shfl_sync(0xffffffffu, qA, d);
            float qb = __shfl_sync(0xffffffffu, qB, d);
            sA0 = fmaf(qa, k0v, sA0);
            sA1 = fmaf(qa, k1v, sA1);
            sB0 = fmaf(qb, k0v, sB0);
            sB1 = fmaf(qb, k1v, sB1);
        }
        // ---- bias + mask + softmax row A ----
        {
            const int xi = i / WS, yi = i - xi * WS;
            float c0, c1 = -1e30f;
            {
                int j = lane, xj = j / WS, yj = j - xj * WS;
                float s = sA0 * scale + pe[(xj - xi + 6) * 13 + (yj - yi + 6)];
                bool dead = (mUL && ((i >= 28) != (j >= 28))) ||
                            (mLR && ((yi >= 4) != (yj >= 4)));
                c0 = dead ? -1e30f : s;
            }
            if (lane < 17) {
                int j = 32 + lane, xj = j / WS, yj = j - xj * WS;
                float s = sA1 * scale + pe[(xj - xi + 6) * 13 + (yj - yi + 6)];
                bool dead = (mUL && ((i >= 28) != (j >= 28))) ||
                            (mLR && ((yi >= 4) != (yj >= 4)));
                c1 = dead ? -1e30f : s;
            }
            float mx = fmaxf(c0, c1);
#pragma unroll
            for (int o = 16; o; o >>= 1) mx = fmaxf(mx, __shfl_xor_sync(0xffffffffu, mx, o));
            float e0 = __expf(c0 - mx);
            float e1 = (lane < 17) ? __expf(c1 - mx) : 0.f;
            float sum = e0 + e1;
#pragma unroll
            for (int o = 16; o; o >>= 1) sum += __shfl_xor_sync(0xffffffffu, sum, o);
            float inv = 1.0f / sum;
            sA0 = e0 * inv; sA1 = e1 * inv;     // reuse as probs
        }
        // ---- bias + mask + softmax row B ----
        if (two) {
            const int xi = i2 / WS, yi = i2 - xi * WS;
            float c0, c1 = -1e30f;
            {
                int j = lane, xj = j / WS, yj = j - xj * WS;
                float s = sB0 * scale + pe[(xj - xi + 6) * 13 + (yj - yi + 6)];
                bool dead = (mUL && ((i2 >= 28) != (j >= 28))) ||
                            (mLR && ((yi >= 4) != (yj >= 4)));
                c0 = dead ? -1e30f : s;
            }
            if (lane < 17) {
                int j = 32 + lane, xj = j / WS, yj = j - xj * WS;
                float s = sB1 * scale + pe[(xj - xi + 6) * 13 + (yj - yi + 6)];
                bool dead = (mUL && ((i2 >= 28) != (j >= 28))) ||
                            (mLR && ((yi >= 4) != (yj >= 4)));
                c1 = dead ? -1e30f : s;
            }
            float mx = fmaxf(c0, c1);
#pragma unroll
            for (int o = 16; o; o >>= 1) mx = fmaxf(mx, __shfl_xor_sync(0xffffffffu, mx, o));
            float e0 = __expf(c0 - mx);
            float e1 = (lane < 17) ? __expf(c1 - mx) : 0.f;
            float sum = e0 + e1;
#pragma unroll
            for (int o = 16; o; o >>= 1) sum += __shfl_xor_sync(0xffffffffu, sum, o);
            float inv = 1.0f / sum;
            sB0 = e0 * inv; sB1 = e1 * inv;
        }
        // ---- AV: lane = d, both rows share v reads ----
        float oA = 0.f, oB = 0.f;
#pragma unroll
        for (int j = 0; j < 32; j++) {
            float vv = v[j * HD + lane];
            oA = fmaf(__shfl_sync(0xffffffffu, sA0, j), vv, oA);
            oB = fmaf(__shfl_sync(0xffffffffu, sB0, j), vv, oB);
        }
#pragma unroll
        for (int j = 0; j < 17; j++) {
            float vv = v[(32 + j) * HD + lane];
            oA = fmaf(__shfl_sync(0xffffffffu, sA1, j), vv, oA);
            oB = fmaf(__shfl_sync(0xffffffffu, sB1, j), vv, oB);
        }
        // ---- store ----
        {
            int h = h0 + i / WS, w = w0 + i % WS;
            g_ao[((b * HW + h) * HW + w) * EMB + head * HD + lane] = oA;
        }
        if (two) {
            int h = h0 + i2 / WS, w = w0 + i2 % WS;
            g_ao[((b * HW + h) * HW + w) * EMB + head * HD + lane] = oB;
        }
    }
}

// ---------------------------------------------------------------------------
// Stage 3: projection GEMM.
// ---------------------------------------------------------------------------
__global__ __launch_bounds__(NTHR) void proj_gemm(const float* __restrict__ wout,
                                                  const float* __restrict__ bout,
                                                  float* __restrict__ out) {
    __shared__ __align__(16) float As[2][BK][BMP];
    __shared__ __align__(16) float Bs[2][BK][BMP];
    const int tid  = threadIdx.x;
    const int row0 = blockIdx.y * BM;
    const int col0 = blockIdx.x * BN;
    const int tr   = (tid & 15) * TM;
    const int tc   = (tid >> 4) * TN;

    unsigned long long acc2[TM][TN/2];
#pragma unroll
    for (int i = 0; i < TM; i++)
#pragma unroll
        for (int j = 0; j < TN/2; j++) acc2[i][j] = 0ull;

    const int lr0 = tid >> 2;
    const int c4  = tid & 3;
    const float* arow[4];
    const float* brow[4];
#pragma unroll
    for (int l = 0; l < 4; l++) {
        int r = lr0 + l * 32;
        arow[l] = g_ao + (row0 + r) * EMB;
        brow[l] = wout + (col0 + r) * EMB;
    }
    float4 sa[4], sb[4];

    GEMM_MAIN_LOOP;

#pragma unroll
    for (int i = 0; i < TM; i++) {
        int m = row0 + tr + i;
        int b = m / 3136, rem = m % 3136, h = rem / HW, w = rem % HW;
        int ho = (h + 3) % HW, wo = (w + 3) % HW;   // roll(+3,+3)
        float* orow = out + ((b * HW + ho) * HW + wo) * EMB + col0 + tc;
#pragma unroll
        for (int j = 0; j < TN/2; j += 2) {
            uint32_t l0, h0_, l1, h1_;
            UNPACK2(l0, h0_, acc2[i][j]);
            UNPACK2(l1, h1_, acc2[i][j+1]);
            float4 bb = *(const float4*)&bout[col0 + tc + 2*j];
            *(float4*)&orow[2*j] = make_float4(__uint_as_float(l0) + bb.x,
                                               __uint_as_float(h0_) + bb.y,
                                               __uint_as_float(l1) + bb.z,
                                               __uint_as_float(h1_) + bb.w);
        }
    }
}

// ---------------------------------------------------------------------------
extern "C" void kernel_launch(void* const* d_in, const int* in_sizes, int n_in,
                              void* d_out, int out_size) {
    const float* x       = (const float*)d_in[0];
    const float* w_qkv   = (const float*)d_in[1];
    const float* pos_emb = (const float*)d_in[2];
    const float* w_out   = (const float*)d_in[3];
    const float* b_out   = (const float*)d_in[4];
    float* out = (float*)d_out;

    dim3 g1(1152 / BN, TOKENS / BM);          // 9 x 392
    qkv_gemm<<<g1, NTHR>>>(x, w_qkv);

    attn_kernel<<<B_ * NWIN * HEADS, 256>>>(pos_emb);

    dim3 g3(EMB / BN, TOKENS / BM);           // 3 x 392
    proj_gemm<<<g3, NTHR>>>(w_out, b_out, out);
}

// round 17
// speedup vs baseline: 1.3059x; 1.0346x over previous
#include <cuda_runtime.h>
#include <cuda_bf16.h>
#include <cstdint>

// ---------------------------------------------------------------------------
// Swin shifted-window attention. R16: GEMMs identical to R14 (guard-proven,
// 1507us total). Attention rewritten shfl-free: f32x2 QK with broadcast-LDS
// q-pairs, smem-prob AV with half-warp row split.
// ---------------------------------------------------------------------------

#define B_     16
#define HW     56
#define EMB    384
#define HEADS  12
#define HD     32
#define WS     7
#define NTOK   49
#define NWIN   64
#define TOKENS (B_*HW*HW)  // 50176

#define BM 128
#define BN 128
#define BK 16
#define TM 8
#define TN 16
#define NTHR 128
#define BMP (BM + 4)

#define KS2 34             // attn k smem row stride (even: aligned LDS.64; 2-way worst)

__device__ float g_q[B_*NWIN*HEADS*NTOK*HD];
__device__ float g_k[B_*NWIN*HEADS*NTOK*HD];
__device__ float g_v[B_*NWIN*HEADS*NTOK*HD];
__device__ float g_ao[TOKENS*EMB];

#define FMA2(C, A, Bv)                                                     \
    asm("fma.rn.f32x2 %0, %1, %2, %0;" : "+l"(C) : "l"(A), "l"(Bv))
#define PACK2(O, LO, HI)                                                   \
    asm("mov.b64 %0, {%1, %2};" : "=l"(O) : "r"(LO), "r"(HI))
#define UNPACK2(LO, HI, I)                                                 \
    asm("mov.b64 {%0, %1}, %2;" : "=r"(LO), "=r"(HI) : "l"(I))

// ---------------------------------------------------------------------------
// GEMM main loop (R14, unchanged).
// ---------------------------------------------------------------------------
#define GEMM_MAIN_LOOP                                                        \
    do {                                                                      \
        _Pragma("unroll")                                                     \
        for (int l = 0; l < 4; l++) {                                         \
            float4 a = *(const float4*)(arow[l] + c4 * 4);                    \
            float4 bv = *(const float4*)(brow[l] + c4 * 4);                   \
            int r = lr0 + l * 32;                                             \
            As[0][c4*4+0][r] = a.x; As[0][c4*4+1][r] = a.y;                   \
            As[0][c4*4+2][r] = a.z; As[0][c4*4+3][r] = a.w;                   \
            Bs[0][c4*4+0][r] = bv.x; Bs[0][c4*4+1][r] = bv.y;                 \
            Bs[0][c4*4+2][r] = bv.z; Bs[0][c4*4+3][r] = bv.w;                 \
        }                                                                     \
        _Pragma("unroll")                                                     \
        for (int l = 0; l < 4; l++) {                                         \
            sa[l] = *(const float4*)(arow[l] + BK + c4 * 4);                  \
            sb[l] = *(const float4*)(brow[l] + BK + c4 * 4);                  \
        }                                                                     \
        _Pragma("unroll 1")                                                   \
        for (int s = 0; s < EMB / BK; s++) {                                  \
            const int cur = s & 1;                                            \
            __syncthreads();                                                  \
            if (s + 1 < EMB / BK) {                                           \
                const int nxt = cur ^ 1;                                      \
                _Pragma("unroll")                                             \
                for (int l = 0; l < 4; l++) {                                 \
                    int r = lr0 + l * 32;                                     \
                    As[nxt][c4*4+0][r] = sa[l].x; As[nxt][c4*4+1][r] = sa[l].y; \
                    As[nxt][c4*4+2][r] = sa[l].z; As[nxt][c4*4+3][r] = sa[l].w; \
                    Bs[nxt][c4*4+0][r] = sb[l].x; Bs[nxt][c4*4+1][r] = sb[l].y; \
                    Bs[nxt][c4*4+2][r] = sb[l].z; Bs[nxt][c4*4+3][r] = sb[l].w; \
                }                                                             \
                if (s + 2 < EMB / BK) {                                       \
                    const int k2 = (s + 2) * BK;                              \
                    _Pragma("unroll")                                         \
                    for (int l = 0; l < 4; l++) {                             \
                        sa[l] = *(const float4*)(arow[l] + k2 + c4 * 4);      \
                        sb[l] = *(const float4*)(brow[l] + k2 + c4 * 4);      \
                    }                                                         \
                }                                                             \
            }                                                                 \
            _Pragma("unroll")                                                 \
            for (int kk = 0; kk < BK; kk++) {                                 \
                float af[TM];                                                 \
                *(float4*)&af[0] = *(float4*)&As[cur][kk][tr];                \
                *(float4*)&af[4] = *(float4*)&As[cur][kk][tr + 4];            \
                unsigned long long b2[TN/2];                                  \
                _Pragma("unroll")                                             \
                for (int j = 0; j < TN/2; j++)                                \
                    b2[j] = *(const unsigned long long*)&Bs[cur][kk][tc + 2*j]; \
                _Pragma("unroll")                                             \
                for (int i = 0; i < TM; i++) {                                \
                    unsigned long long a2;                                    \
                    PACK2(a2, __float_as_uint(af[i]), __float_as_uint(af[i])); \
                    _Pragma("unroll")                                         \
                    for (int j = 0; j < TN/2; j++) FMA2(acc2[i][j], a2, b2[j]); \
                }                                                             \
            }                                                                 \
        }                                                                     \
    } while (0)

// ---------------------------------------------------------------------------
// Stage 1: QKV GEMM (identical to R14).
// ---------------------------------------------------------------------------
__global__ __launch_bounds__(NTHR) void qkv_gemm(const float* __restrict__ x,
                                                 const float* __restrict__ wqkv) {
    __shared__ __align__(16) float As[2][BK][BMP];
    __shared__ __align__(16) float Bs[2][BK][BMP];
    const int tid  = threadIdx.x;
    const int row0 = blockIdx.y * BM;
    const int col0 = blockIdx.x * BN;
    const int tr   = (tid & 15) * TM;
    const int tc   = (tid >> 4) * TN;

    unsigned long long acc2[TM][TN/2];
#pragma unroll
    for (int i = 0; i < TM; i++)
#pragma unroll
        for (int j = 0; j < TN/2; j++) acc2[i][j] = 0ull;

    const int lr0 = tid >> 2;
    const int c4  = tid & 3;
    const float* arow[4];
    const float* brow[4];
#pragma unroll
    for (int l = 0; l < 4; l++) {
        int r = lr0 + l * 32;
        int m = row0 + r;
        int b = m / 3136, rem = m % 3136, h = rem / HW, w = rem % HW;
        int hs = (h + 3) % HW, ws = (w + 3) % HW;   // roll(-3,-3)
        arow[l] = x + ((b * HW + hs) * HW + ws) * EMB;
        brow[l] = wqkv + (col0 + r) * EMB;
    }
    float4 sa[4], sb[4];

    GEMM_MAIN_LOOP;

    const int sel = col0 / EMB;                   // 0:q 1:k 2:v
    float* dst = (sel == 0) ? g_q : (sel == 1) ? g_k : g_v;
    const int local = col0 + tc - sel * EMB;
    const int head  = local >> 5;
    const int d0    = local & 31;
#pragma unroll
    for (int i = 0; i < TM; i++) {
        int m = row0 + tr + i;
        int b = m / 3136, rem = m % 3136, h = rem / HW, w = rem % HW;
        int win = (h / WS) * 8 + (w / WS);
        int n   = (h % WS) * WS + (w % WS);
        float* drow = dst + (b * NWIN + win) * (HEADS * NTOK * HD)
                          + head * (NTOK * HD) + n * HD + d0;
#pragma unroll
        for (int j = 0; j < TN/2; j += 2) {
            uint32_t l0, h0_, l1, h1_;
            UNPACK2(l0, h0_, acc2[i][j]);
            UNPACK2(l1, h1_, acc2[i][j+1]);
            *(float4*)&drow[2*j] = make_float4(__uint_as_float(l0), __uint_as_float(h0_),
                                               __uint_as_float(l1), __uint_as_float(h1_));
        }
    }
}

// ---------------------------------------------------------------------------
// Stage 2: attention, shfl-free. One block per (b,win,head), 256 thr, 8 warps.
// Warp handles rows (i, i+8) per iteration; f32x2 QK with broadcast q-pair
// LDS; AV via per-warp smem probs, half-warp per row, lane = d-pair.
// ---------------------------------------------------------------------------
__global__ __launch_bounds__(256) void attn_kernel(const float* __restrict__ pe_g) {
    __shared__ __align__(16) float q[NTOK * HD];
    __shared__ __align__(16) float ks[64 * KS2];
    __shared__ __align__(16) float v[NTOK * HD];
    __shared__ __align__(16) float ps[8][2][64];
    __shared__ float pe[169];

    const int blk = blockIdx.x;
    const int tid = threadIdx.x;
    const float* qp = g_q + blk * (NTOK * HD);
    const float* kp = g_k + blk * (NTOK * HD);
    const float* vp = g_v + blk * (NTOK * HD);

    for (int i4 = tid; i4 < NTOK * HD / 4; i4 += 256) {
        ((float4*)q)[i4] = ((const float4*)qp)[i4];
        ((float4*)v)[i4] = ((const float4*)vp)[i4];
    }
    // k rows with stride KS2 (aligned for LDS.64 pairs)
    for (int idx = tid; idx < NTOK * HD; idx += 256) {
        ks[(idx >> 5) * KS2 + (idx & 31)] = kp[idx];
    }
    // zero pad rows 49..63 (read by lanes >= 17, values discarded)
    for (int idx = tid; idx < (64 - NTOK) * KS2; idx += 256) {
        ks[NTOK * KS2 + idx] = 0.f;
    }
    if (tid < 169) pe[tid] = pe_g[tid];
    __syncthreads();

    const int head = blk % HEADS;
    const int bwin = blk / HEADS;
    const int win  = bwin & 63;
    const int b    = bwin >> 6;
    const bool mUL = (win >= 56);
    const bool mLR = ((win & 7) == 7);
    const float scale = 0.17677669529663687f;  // 1/sqrt(32)
    const int warp = tid >> 5, lane = tid & 31;
    const int h0 = (win >> 3) * WS, w0 = (win & 7) * WS;

    for (int i = warp; i < NTOK; i += 16) {
        const int i2 = i + 8;
        const bool two = (i2 < NTOK);           // warp-uniform
        // ---- QK: f32x2 over d-pairs; q pairs broadcast from smem ----
        unsigned long long sA0 = 0ull, sA1 = 0ull, sB0 = 0ull, sB1 = 0ull;
#pragma unroll
        for (int dp = 0; dp < 16; dp++) {
            unsigned long long k2a = *(const unsigned long long*)&ks[lane * KS2 + 2*dp];
            unsigned long long k2b = *(const unsigned long long*)&ks[(32 + lane) * KS2 + 2*dp];
            unsigned long long qA2 = *(const unsigned long long*)&q[i * HD + 2*dp];
            FMA2(sA0, qA2, k2a);
            FMA2(sA1, qA2, k2b);
            if (two) {
                unsigned long long qB2 = *(const unsigned long long*)&q[i2 * HD + 2*dp];
                FMA2(sB0, qB2, k2a);
                FMA2(sB1, qB2, k2b);
            }
        }
        uint32_t ulo, uhi;
        UNPACK2(ulo, uhi, sA0);
        float vA0 = __uint_as_float(ulo) + __uint_as_float(uhi);
        UNPACK2(ulo, uhi, sA1);
        float vA1 = __uint_as_float(ulo) + __uint_as_float(uhi);
        UNPACK2(ulo, uhi, sB0);
        float vB0 = __uint_as_float(ulo) + __uint_as_float(uhi);
        UNPACK2(ulo, uhi, sB1);
        float vB1 = __uint_as_float(ulo) + __uint_as_float(uhi);

        // ---- bias + mask + softmax row A ----
        float pA0, pA1;
        {
            const int xi = i / WS, yi = i - xi * WS;
            float c0, c1 = -1e30f;
            {
                int j = lane, xj = j / WS, yj = j - xj * WS;
                float s = vA0 * scale + pe[(xj - xi + 6) * 13 + (yj - yi + 6)];
                bool dead = (mUL && ((i >= 28) != (j >= 28))) ||
                            (mLR && ((yi >= 4) != (yj >= 4)));
                c0 = dead ? -1e30f : s;
            }
            if (lane < 17) {
                int j = 32 + lane, xj = j / WS, yj = j - xj * WS;
                float s = vA1 * scale + pe[(xj - xi + 6) * 13 + (yj - yi + 6)];
                bool dead = (mUL && ((i >= 28) != (j >= 28))) ||
                            (mLR && ((yi >= 4) != (yj >= 4)));
                c1 = dead ? -1e30f : s;
            }
            float mx = fmaxf(c0, c1);
#pragma unroll
            for (int o = 16; o; o >>= 1) mx = fmaxf(mx, __shfl_xor_sync(0xffffffffu, mx, o));
            float e0 = __expf(c0 - mx);
            float e1 = (lane < 17) ? __expf(c1 - mx) : 0.f;
            float sum = e0 + e1;
#pragma unroll
            for (int o = 16; o; o >>= 1) sum += __shfl_xor_sync(0xffffffffu, sum, o);
            float inv = 1.0f / sum;
            pA0 = e0 * inv; pA1 = e1 * inv;
        }
        // ---- bias + mask + softmax row B ----
        float pB0 = 0.f, pB1 = 0.f;
        if (two) {
            const int xi = i2 / WS, yi = i2 - xi * WS;
            float c0, c1 = -1e30f;
            {
                int j = lane, xj = j / WS, yj = j - xj * WS;
                float s = vB0 * scale + pe[(xj - xi + 6) * 13 + (yj - yi + 6)];
                bool dead = (mUL && ((i2 >= 28) != (j >= 28))) ||
                            (mLR && ((yi >= 4) != (yj >= 4)));
                c0 = dead ? -1e30f : s;
            }
            if (lane < 17) {
                int j = 32 + lane, xj = j / WS, yj = j - xj * WS;
                float s = vB1 * scale + pe[(xj - xi + 6) * 13 + (yj - yi + 6)];
                bool dead = (mUL && ((i2 >= 28) != (j >= 28))) ||
                            (mLR && ((yi >= 4) != (yj >= 4)));
                c1 = dead ? -1e30f : s;
            }
            float mx = fmaxf(c0, c1);
#pragma unroll
            for (int o = 16; o; o >>= 1) mx = fmaxf(mx, __shfl_xor_sync(0xffffffffu, mx, o));
            float e0 = __expf(c0 - mx);
            float e1 = (lane < 17) ? __expf(c1 - mx) : 0.f;
            float sum = e0 + e1;
#pragma unroll
            for (int o = 16; o; o >>= 1) sum += __shfl_xor_sync(0xffffffffu, sum, o);
            float inv = 1.0f / sum;
            pB0 = e0 * inv; pB1 = e1 * inv;
        }
        // ---- publish probs to warp-local smem ----
        ps[warp][0][lane] = pA0;
        ps[warp][1][lane] = pB0;
        if (lane < 17) {
            ps[warp][0][32 + lane] = pA1;
            ps[warp][1][32 + lane] = pB1;
        }
        __syncwarp();
        // ---- AV: half-warp per row, lane covers d-pair ----
        const int r  = lane >> 4;               // 0 -> row i, 1 -> row i2
        const int dp = lane & 15;
        unsigned long long o2 = 0ull;
#pragma unroll
        for (int j = 0; j < NTOK; j++) {
            unsigned long long v2 = *(const unsigned long long*)&v[j * HD + 2*dp];
            uint32_t pb = __float_as_uint(ps[warp][r][j]);
            unsigned long long p2;
            PACK2(p2, pb, pb);
            FMA2(o2, p2, v2);
        }
        UNPACK2(ulo, uhi, o2);
        const int row = r ? i2 : i;
        if (r == 0 || two) {
            int h = h0 + row / WS, w = w0 + row % WS;
            *(float2*)&g_ao[((b * HW + h) * HW + w) * EMB + head * HD + 2*dp] =
                make_float2(__uint_as_float(ulo), __uint_as_float(uhi));
        }
        __syncwarp();   // ps reused next iteration
    }
}

// ---------------------------------------------------------------------------
// Stage 3: projection GEMM (identical to R14).
// ---------------------------------------------------------------------------
__global__ __launch_bounds__(NTHR) void proj_gemm(const float* __restrict__ wout,
                                                  const float* __restrict__ bout,
                                                  float* __restrict__ out) {
    __shared__ __align__(16) float As[2][BK][BMP];
    __shared__ __align__(16) float Bs[2][BK][BMP];
    const int tid  = threadIdx.x;
    const int row0 = blockIdx.y * BM;
    const int col0 = blockIdx.x * BN;
    const int tr   = (tid & 15) * TM;
    const int tc   = (tid >> 4) * TN;

    unsigned long long acc2[TM][TN/2];
#pragma unroll
    for (int i = 0; i < TM; i++)
#pragma unroll
        for (int j = 0; j < TN/2; j++) acc2[i][j] = 0ull;

    const int lr0 = tid >> 2;
    const int c4  = tid & 3;
    const float* arow[4];
    const float* brow[4];
#pragma unroll
    for (int l = 0; l < 4; l++) {
        int r = lr0 + l * 32;
        arow[l] = g_ao + (row0 + r) * EMB;
        brow[l] = wout + (col0 + r) * EMB;
    }
    float4 sa[4], sb[4];

    GEMM_MAIN_LOOP;

#pragma unroll
    for (int i = 0; i < TM; i++) {
        int m = row0 + tr + i;
        int b = m / 3136, rem = m % 3136, h = rem / HW, w = rem % HW;
        int ho = (h + 3) % HW, wo = (w + 3) % HW;   // roll(+3,+3)
        float* orow = out + ((b * HW + ho) * HW + wo) * EMB + col0 + tc;
#pragma unroll
        for (int j = 0; j < TN/2; j += 2) {
            uint32_t l0, h0_, l1, h1_;
            UNPACK2(l0, h0_, acc2[i][j]);
            UNPACK2(l1, h1_, acc2[i][j+1]);
            float4 bb = *(const float4*)&bout[col0 + tc + 2*j];
            *(float4*)&orow[2*j] = make_float4(__uint_as_float(l0) + bb.x,
                                               __uint_as_float(h0_) + bb.y,
                                               __uint_as_float(l1) + bb.z,
                                               __uint_as_float(h1_) + bb.w);
        }
    }
}

// ---------------------------------------------------------------------------
extern "C" void kernel_launch(void* const* d_in, const int* in_sizes, int n_in,
                              void* d_out, int out_size) {
    const float* x       = (const float*)d_in[0];
    const float* w_qkv   = (const float*)d_in[1];
    const float* pos_emb = (const float*)d_in[2];
    const float* w_out   = (const float*)d_in[3];
    const float* b_out   = (const float*)d_in[4];
    float* out = (float*)d_out;

    dim3 g1(1152 / BN, TOKENS / BM);          // 9 x 392
    qkv_gemm<<<g1, NTHR>>>(x, w_qkv);

    attn_kernel<<<B_ * NWIN * HEADS, 256>>>(pos_emb);

    dim3 g3(EMB / BN, TOKENS / BM);           // 3 x 392
    proj_gemm<<<g3, NTHR>>>(w_out, b_out, out);
}